// round 3
// baseline (speedup 1.0000x reference)
#include <cuda_runtime.h>
#include <math.h>

#define N_NODES 100000
#define N_EDGES 1600000
#define NFEAT 512
#define HID 128
#define NCLS 40

#define SCAN_B 1024
#define NBLK ((N_NODES + SCAN_B - 1) / SCAN_B)   // 98

// ---------------- device scratch (no allocations allowed) ----------------
__device__ int   g_cnt[N_NODES];
__device__ int   g_start[N_NODES];
__device__ int   g_cursor[N_NODES];
__device__ float g_inv_sqrt[N_NODES];
__device__ float g_invdeg[N_NODES];
__device__ int   g_blocksum[NBLK];
__device__ int   g_blockoff[NBLK];
__device__ int2  g_edge[N_EDGES];                // .x = src, .y = coef bits
__device__ float g_h1[(size_t)N_NODES * HID];    // x @ W1
__device__ float g_a1[(size_t)N_NODES * HID];    // relu(conv1)
__device__ float g_h2[(size_t)N_NODES * NCLS];   // a1 @ W2

// ---------------- CSR build ----------------
__global__ void zero_cnt_kernel() {
    int i = blockIdx.x * blockDim.x + threadIdx.x;
    if (i < N_NODES) g_cnt[i] = 0;
}

__global__ void count_kernel(const int* __restrict__ dst) {
    int e = blockIdx.x * blockDim.x + threadIdx.x;
    if (e < N_EDGES) atomicAdd(&g_cnt[dst[e]], 1);
}

__global__ void scan_blocks_kernel() {
    __shared__ int s[SCAN_B];
    int tid = threadIdx.x;
    int i = blockIdx.x * SCAN_B + tid;
    int v = (i < N_NODES) ? g_cnt[i] : 0;
    s[tid] = v;
    __syncthreads();
    #pragma unroll
    for (int off = 1; off < SCAN_B; off <<= 1) {
        int t = (tid >= off) ? s[tid - off] : 0;
        __syncthreads();
        s[tid] += t;
        __syncthreads();
    }
    if (i < N_NODES) g_start[i] = s[tid] - v;       // exclusive within block
    if (tid == SCAN_B - 1) g_blocksum[blockIdx.x] = s[tid];
}

__global__ void scan_sums_kernel() {
    __shared__ int s[128];
    int tid = threadIdx.x;
    int v = (tid < NBLK) ? g_blocksum[tid] : 0;
    s[tid] = v;
    __syncthreads();
    #pragma unroll
    for (int off = 1; off < 128; off <<= 1) {
        int t = (tid >= off) ? s[tid - off] : 0;
        __syncthreads();
        s[tid] += t;
        __syncthreads();
    }
    if (tid < NBLK) g_blockoff[tid] = s[tid] - v;   // exclusive
}

__global__ void finalize_nodes_kernel() {
    int i = blockIdx.x * blockDim.x + threadIdx.x;
    if (i >= N_NODES) return;
    g_start[i] += g_blockoff[i >> 10];
    g_cursor[i] = 0;
    float deg = (float)g_cnt[i] + 1.0f;
    g_inv_sqrt[i] = rsqrtf(deg);
    g_invdeg[i]   = 1.0f / deg;
}

__global__ void scatter_kernel(const int* __restrict__ src_a,
                               const int* __restrict__ dst_a) {
    int e = blockIdx.x * blockDim.x + threadIdx.x;
    if (e >= N_EDGES) return;
    int s = src_a[e];
    int d = dst_a[e];
    int pos = g_start[d] + atomicAdd(&g_cursor[d], 1);
    float cf = g_inv_sqrt[s] * g_inv_sqrt[d];
    g_edge[pos] = make_int2(s, __float_as_int(cf));
}

// ---------------- GEMM1: h1 = x @ W1  (100000x512 @ 512x128) ----------------
// Block tile 64x128, K tile 16, 128 threads, 8x8 per thread.
__global__ __launch_bounds__(128) void gemm1_kernel(const float* __restrict__ A,
                                                    const float* __restrict__ B) {
    __shared__ float As[16][72];     // [k][m], stride 72 keeps float4 alignment
    __shared__ float Bs[16][128];    // [k][n]
    int tid = threadIdx.x;
    int block_m = blockIdx.x * 64;
    int m0 = (tid >> 4) * 8;
    int n0 = (tid & 15) * 8;
    float acc[8][8] = {};

    for (int k0 = 0; k0 < NFEAT; k0 += 16) {
        // A tile: 64x16 = 256 float4, 2 per thread (transposed into smem)
        #pragma unroll
        for (int r = 0; r < 2; r++) {
            int idx = tid + r * 128;
            int row = idx >> 2;
            int kc  = (idx & 3) * 4;
            float4 v = make_float4(0.f, 0.f, 0.f, 0.f);
            int gr = block_m + row;
            if (gr < N_NODES)
                v = *(const float4*)&A[(size_t)gr * NFEAT + k0 + kc];
            As[kc + 0][row] = v.x; As[kc + 1][row] = v.y;
            As[kc + 2][row] = v.z; As[kc + 3][row] = v.w;
        }
        // B tile: 16x128 = 512 float4, 4 per thread
        #pragma unroll
        for (int r = 0; r < 4; r++) {
            int idx = tid + r * 128;
            int row = idx >> 5;
            int col = (idx & 31) * 4;
            *(float4*)&Bs[row][col] = *(const float4*)&B[(size_t)(k0 + row) * HID + col];
        }
        __syncthreads();
        #pragma unroll
        for (int k = 0; k < 16; k++) {
            float a[8], b[8];
            *(float4*)&a[0] = *(float4*)&As[k][m0];
            *(float4*)&a[4] = *(float4*)&As[k][m0 + 4];
            *(float4*)&b[0] = *(float4*)&Bs[k][n0];
            *(float4*)&b[4] = *(float4*)&Bs[k][n0 + 4];
            #pragma unroll
            for (int i = 0; i < 8; i++)
                #pragma unroll
                for (int j = 0; j < 8; j++)
                    acc[i][j] += a[i] * b[j];
        }
        __syncthreads();
    }
    #pragma unroll
    for (int i = 0; i < 8; i++) {
        int gr = block_m + m0 + i;
        if (gr < N_NODES) {
            *(float4*)&g_h1[(size_t)gr * HID + n0]     = *(float4*)&acc[i][0];
            *(float4*)&g_h1[(size_t)gr * HID + n0 + 4] = *(float4*)&acc[i][4];
        }
    }
}

// ---------------- agg1: a1 = relu(sum_e coef*h1[src] + h1*invdeg + b1) ------
// One warp per node, float4 lanes cover the 128-dim row.
__global__ void agg1_kernel(const float* __restrict__ b1) {
    int gw = (blockIdx.x * blockDim.x + threadIdx.x) >> 5;
    int lane = threadIdx.x & 31;
    if (gw >= N_NODES) return;
    int node = gw;
    const float4* H = (const float4*)g_h1;
    float4 self = H[node * 32 + lane];
    float sd = g_invdeg[node];
    float4 acc;
    acc.x = self.x * sd; acc.y = self.y * sd;
    acc.z = self.z * sd; acc.w = self.w * sd;
    int s = g_start[node];
    int c = g_cnt[node];
    for (int e = 0; e < c; e++) {
        int2 ed = g_edge[s + e];
        int src  = ed.x;
        float cf = __int_as_float(ed.y);
        float4 v = H[src * 32 + lane];
        acc.x += v.x * cf; acc.y += v.y * cf;
        acc.z += v.z * cf; acc.w += v.w * cf;
    }
    float4 bb = ((const float4*)b1)[lane];
    acc.x = fmaxf(acc.x + bb.x, 0.f);
    acc.y = fmaxf(acc.y + bb.y, 0.f);
    acc.z = fmaxf(acc.z + bb.z, 0.f);
    acc.w = fmaxf(acc.w + bb.w, 0.f);
    ((float4*)g_a1)[node * 32 + lane] = acc;
}

// ---------------- GEMM2: h2 = a1 @ W2 (100000x128 @ 128x40) ----------------
// 128 threads, 32 nodes per block, 10 cols per thread.
__global__ __launch_bounds__(128) void gemm2_kernel(const float* __restrict__ W2) {
    __shared__ float Ws[HID * NCLS];   // [k][c] stride 40
    __shared__ float As[32][132];      // pad to kill bank conflicts
    int tid = threadIdx.x;
    for (int i = tid; i < HID * NCLS; i += 128) Ws[i] = W2[i];
    int base = blockIdx.x * 32;
    for (int i = tid; i < 32 * HID; i += 128) {
        int row = i >> 7;
        int col = i & 127;
        int gr = base + row;
        As[row][col] = (gr < N_NODES) ? g_a1[(size_t)gr * HID + col] : 0.f;
    }
    __syncthreads();
    int nl = tid >> 2;
    int cg = (tid & 3) * 10;
    float acc[10] = {};
    #pragma unroll 8
    for (int k = 0; k < HID; k++) {
        float a = As[nl][k];
        #pragma unroll
        for (int j = 0; j < 10; j++)
            acc[j] += a * Ws[k * NCLS + cg + j];
    }
    int gr = base + nl;
    if (gr < N_NODES) {
        #pragma unroll
        for (int j = 0; j < 10; j++)
            g_h2[(size_t)gr * NCLS + cg + j] = acc[j];
    }
}

// ---------------- agg2 + bias + log_softmax ----------------
// One warp per node. Lane l owns class l; lanes 0..7 also own class 32+l.
__global__ void agg2_kernel(const float* __restrict__ b2, float* __restrict__ out) {
    int gw = (blockIdx.x * blockDim.x + threadIdx.x) >> 5;
    int lane = threadIdx.x & 31;
    if (gw >= N_NODES) return;
    int node = gw;
    const float* H = g_h2;
    float sd = g_invdeg[node];
    float acc0 = H[(size_t)node * NCLS + lane] * sd;
    float acc1 = (lane < 8) ? H[(size_t)node * NCLS + 32 + lane] * sd : 0.f;
    int s = g_start[node];
    int c = g_cnt[node];
    for (int e = 0; e < c; e++) {
        int2 ed = g_edge[s + e];
        int src  = ed.x;
        float cf = __int_as_float(ed.y);
        acc0 += H[(size_t)src * NCLS + lane] * cf;
        if (lane < 8) acc1 += H[(size_t)src * NCLS + 32 + lane] * cf;
    }
    acc0 += b2[lane];
    if (lane < 8) acc1 += b2[32 + lane];
    // log_softmax over 40 classes
    float m = acc0;
    if (lane < 8) m = fmaxf(m, acc1);
    #pragma unroll
    for (int off = 16; off > 0; off >>= 1)
        m = fmaxf(m, __shfl_xor_sync(0xffffffffu, m, off));
    float sum = expf(acc0 - m) + ((lane < 8) ? expf(acc1 - m) : 0.f);
    #pragma unroll
    for (int off = 16; off > 0; off >>= 1)
        sum += __shfl_xor_sync(0xffffffffu, sum, off);
    float lse = m + logf(sum);
    out[(size_t)node * NCLS + lane] = acc0 - lse;
    if (lane < 8) out[(size_t)node * NCLS + 32 + lane] = acc1 - lse;
}

// ---------------- launch ----------------
extern "C" void kernel_launch(void* const* d_in, const int* in_sizes, int n_in,
                              void* d_out, int out_size) {
    const float* x   = (const float*)d_in[0];
    const int*   ei  = (const int*)d_in[1];
    const float* W1  = (const float*)d_in[2];
    const float* b1  = (const float*)d_in[3];
    const float* W2  = (const float*)d_in[4];
    const float* b2  = (const float*)d_in[5];
    float* out = (float*)d_out;
    const int* src = ei;
    const int* dst = ei + N_EDGES;

    int nb_n = (N_NODES + 255) / 256;
    int nb_e = (N_EDGES + 255) / 256;

    zero_cnt_kernel<<<nb_n, 256>>>();
    count_kernel<<<nb_e, 256>>>(dst);
    scan_blocks_kernel<<<NBLK, SCAN_B>>>();
    scan_sums_kernel<<<1, 128>>>();
    finalize_nodes_kernel<<<nb_n, 256>>>();
    scatter_kernel<<<nb_e, 256>>>(src, dst);

    gemm1_kernel<<<(N_NODES + 63) / 64, 128>>>(x, W1);

    // one warp per node, 8 warps per block
    agg1_kernel<<<(N_NODES + 7) / 8, 256>>>(b1);

    gemm2_kernel<<<(N_NODES + 31) / 32, 128>>>(W2);

    agg2_kernel<<<(N_NODES + 7) / 8, 256>>>(b2, out);
}

// round 4
// speedup vs baseline: 1.5322x; 1.5322x over previous
#include <cuda_runtime.h>
#include <math.h>
#include <stdint.h>

#define N_NODES 100000
#define N_EDGES 1600000
#define NFEAT 512
#define HID 128
#define NCLS 40

#define SCAN_B 1024
#define NBLK ((N_NODES + SCAN_B - 1) / SCAN_B)   // 98

// ---------------- device scratch (no allocations allowed) ----------------
__device__ int   g_cnt[N_NODES];
__device__ int   g_start[N_NODES];
__device__ int   g_cursor[N_NODES];
__device__ float g_inv_sqrt[N_NODES];
__device__ float g_invdeg[N_NODES];
__device__ int   g_blocksum[NBLK];
__device__ int   g_blockoff[NBLK];
__device__ int2  g_edge[N_EDGES];                // .x = src, .y = coef bits
__device__ float g_h1[(size_t)N_NODES * HID];    // x @ W1
__device__ float g_a1[(size_t)N_NODES * HID];    // relu(conv1)
__device__ float g_h2[(size_t)N_NODES * NCLS];   // a1 @ W2

// ---------------- CSR build ----------------
__global__ void zero_cnt_kernel() {
    int i = blockIdx.x * blockDim.x + threadIdx.x;
    if (i < N_NODES) g_cnt[i] = 0;
}

__global__ void count_kernel(const int* __restrict__ dst) {
    int e = blockIdx.x * blockDim.x + threadIdx.x;
    if (e < N_EDGES) atomicAdd(&g_cnt[dst[e]], 1);
}

__global__ void scan_blocks_kernel() {
    __shared__ int s[SCAN_B];
    int tid = threadIdx.x;
    int i = blockIdx.x * SCAN_B + tid;
    int v = (i < N_NODES) ? g_cnt[i] : 0;
    s[tid] = v;
    __syncthreads();
    #pragma unroll
    for (int off = 1; off < SCAN_B; off <<= 1) {
        int t = (tid >= off) ? s[tid - off] : 0;
        __syncthreads();
        s[tid] += t;
        __syncthreads();
    }
    if (i < N_NODES) g_start[i] = s[tid] - v;       // exclusive within block
    if (tid == SCAN_B - 1) g_blocksum[blockIdx.x] = s[tid];
}

__global__ void scan_sums_kernel() {
    __shared__ int s[128];
    int tid = threadIdx.x;
    int v = (tid < NBLK) ? g_blocksum[tid] : 0;
    s[tid] = v;
    __syncthreads();
    #pragma unroll
    for (int off = 1; off < 128; off <<= 1) {
        int t = (tid >= off) ? s[tid - off] : 0;
        __syncthreads();
        s[tid] += t;
        __syncthreads();
    }
    if (tid < NBLK) g_blockoff[tid] = s[tid] - v;   // exclusive
}

__global__ void finalize_nodes_kernel() {
    int i = blockIdx.x * blockDim.x + threadIdx.x;
    if (i >= N_NODES) return;
    g_start[i] += g_blockoff[i >> 10];
    g_cursor[i] = 0;
    float deg = (float)g_cnt[i] + 1.0f;
    g_inv_sqrt[i] = rsqrtf(deg);
    g_invdeg[i]   = 1.0f / deg;
}

__global__ void scatter_kernel(const int* __restrict__ src_a,
                               const int* __restrict__ dst_a) {
    int e = blockIdx.x * blockDim.x + threadIdx.x;
    if (e >= N_EDGES) return;
    int s = src_a[e];
    int d = dst_a[e];
    int pos = g_start[d] + atomicAdd(&g_cursor[d], 1);
    float cf = g_inv_sqrt[s] * g_inv_sqrt[d];
    g_edge[pos] = make_int2(s, __float_as_int(cf));
}

// ---------------- GEMM1: h1 = x @ W1 via tf32 mma.sync ----------------
// Block tile 128x128, K tile 32, 256 threads = 8 warps (4 M x 2 N).
// Each warp: 32x64 via 2x8 grid of m16n8k8 mma tiles.

__device__ __forceinline__ uint32_t f2tf32(float f) {
    uint32_t u;
    asm("cvt.rna.tf32.f32 %0, %1;" : "=r"(u) : "f"(f));
    return u;
}

__device__ __forceinline__ void mma_tf32(float* c, const uint32_t* a,
                                         uint32_t b0, uint32_t b1) {
    asm volatile(
        "mma.sync.aligned.m16n8k8.row.col.f32.tf32.tf32.f32 "
        "{%0,%1,%2,%3}, {%4,%5,%6,%7}, {%8,%9}, {%0,%1,%2,%3};"
        : "+f"(c[0]), "+f"(c[1]), "+f"(c[2]), "+f"(c[3])
        : "r"(a[0]), "r"(a[1]), "r"(a[2]), "r"(a[3]), "r"(b0), "r"(b1));
}

#define G1_AS 36    // A smem row stride (pad): (4m+k)%32 bijective -> conflict-free
#define G1_BS 136   // B smem row stride (pad): (8k+n)%32 bijective -> conflict-free

__global__ __launch_bounds__(256) void gemm1_mma_kernel(const float* __restrict__ A,
                                                        const float* __restrict__ B) {
    __shared__ uint32_t As[128 * G1_AS];  // [m][k] tf32 bits
    __shared__ uint32_t Bs[32 * G1_BS];   // [k][n] tf32 bits
    const int tid  = threadIdx.x;
    const int lane = tid & 31;
    const int wid  = tid >> 5;
    const int wm   = wid & 3;       // warp M index (0..3) -> 32 rows
    const int wn   = wid >> 2;      // warp N index (0..1) -> 64 cols
    const int g    = lane >> 2;     // groupID
    const int tg   = lane & 3;      // thread-in-group
    const int bm0  = blockIdx.x * 128;

    float acc[2][8][4];
    #pragma unroll
    for (int i = 0; i < 2; i++)
        #pragma unroll
        for (int j = 0; j < 8; j++)
            #pragma unroll
            for (int r = 0; r < 4; r++) acc[i][j][r] = 0.f;

    for (int k0 = 0; k0 < NFEAT; k0 += 32) {
        // A tile: 128x32 floats = 1024 float4, 4 per thread
        #pragma unroll
        for (int r = 0; r < 4; r++) {
            int idx = tid + r * 256;        // 0..1023
            int row = idx >> 3;             // 8 float4 per row
            int col = (idx & 7) * 4;
            int gr  = bm0 + row;
            float4 v = make_float4(0.f, 0.f, 0.f, 0.f);
            if (gr < N_NODES)
                v = *(const float4*)&A[(size_t)gr * NFEAT + k0 + col];
            uint32_t* p = &As[row * G1_AS + col];
            p[0] = f2tf32(v.x); p[1] = f2tf32(v.y);
            p[2] = f2tf32(v.z); p[3] = f2tf32(v.w);
        }
        // B tile: 32x128 floats = 1024 float4, 4 per thread
        #pragma unroll
        for (int r = 0; r < 4; r++) {
            int idx = tid + r * 256;
            int row = idx >> 5;             // 32 float4 per row
            int col = (idx & 31) * 4;
            float4 v = *(const float4*)&B[(size_t)(k0 + row) * HID + col];
            uint32_t* p = &Bs[row * G1_BS + col];
            p[0] = f2tf32(v.x); p[1] = f2tf32(v.y);
            p[2] = f2tf32(v.z); p[3] = f2tf32(v.w);
        }
        __syncthreads();

        #pragma unroll
        for (int kc = 0; kc < 32; kc += 8) {
            uint32_t af[2][4];
            #pragma unroll
            for (int i = 0; i < 2; i++) {
                int m = wm * 32 + i * 16;
                af[i][0] = As[(m + g)     * G1_AS + kc + tg];
                af[i][1] = As[(m + 8 + g) * G1_AS + kc + tg];
                af[i][2] = As[(m + g)     * G1_AS + kc + tg + 4];
                af[i][3] = As[(m + 8 + g) * G1_AS + kc + tg + 4];
            }
            #pragma unroll
            for (int j = 0; j < 8; j++) {
                int n = wn * 64 + j * 8;
                uint32_t b0 = Bs[(kc + tg)     * G1_BS + n + g];
                uint32_t b1 = Bs[(kc + tg + 4) * G1_BS + n + g];
                mma_tf32(acc[0][j], af[0], b0, b1);
                mma_tf32(acc[1][j], af[1], b0, b1);
            }
        }
        __syncthreads();
    }

    // epilogue: c0/c1 -> (row=g, col=2*tg), c2/c3 -> (row=g+8)
    #pragma unroll
    for (int i = 0; i < 2; i++) {
        #pragma unroll
        for (int j = 0; j < 8; j++) {
            int col = wn * 64 + j * 8 + tg * 2;
            int r0  = bm0 + wm * 32 + i * 16 + g;
            int r1  = r0 + 8;
            if (r0 < N_NODES)
                *(float2*)&g_h1[(size_t)r0 * HID + col] =
                    make_float2(acc[i][j][0], acc[i][j][1]);
            if (r1 < N_NODES)
                *(float2*)&g_h1[(size_t)r1 * HID + col] =
                    make_float2(acc[i][j][2], acc[i][j][3]);
        }
    }
}

// ---------------- agg1: a1 = relu(sum_e coef*h1[src] + h1*invdeg + b1) ------
__global__ void agg1_kernel(const float* __restrict__ b1) {
    int gw = (blockIdx.x * blockDim.x + threadIdx.x) >> 5;
    int lane = threadIdx.x & 31;
    if (gw >= N_NODES) return;
    int node = gw;
    const float4* H = (const float4*)g_h1;
    float4 self = H[node * 32 + lane];
    float sd = g_invdeg[node];
    float4 acc;
    acc.x = self.x * sd; acc.y = self.y * sd;
    acc.z = self.z * sd; acc.w = self.w * sd;
    int s = g_start[node];
    int c = g_cnt[node];
    for (int e = 0; e < c; e++) {
        int2 ed = g_edge[s + e];
        int src  = ed.x;
        float cf = __int_as_float(ed.y);
        float4 v = H[src * 32 + lane];
        acc.x += v.x * cf; acc.y += v.y * cf;
        acc.z += v.z * cf; acc.w += v.w * cf;
    }
    float4 bb = ((const float4*)b1)[lane];
    acc.x = fmaxf(acc.x + bb.x, 0.f);
    acc.y = fmaxf(acc.y + bb.y, 0.f);
    acc.z = fmaxf(acc.z + bb.z, 0.f);
    acc.w = fmaxf(acc.w + bb.w, 0.f);
    ((float4*)g_a1)[node * 32 + lane] = acc;
}

// ---------------- GEMM2: h2 = a1 @ W2 (100000x128 @ 128x40), fp32 ----------
__global__ __launch_bounds__(128) void gemm2_kernel(const float* __restrict__ W2) {
    __shared__ float Ws[HID * NCLS];
    __shared__ float As2[32][132];
    int tid = threadIdx.x;
    for (int i = tid; i < HID * NCLS; i += 128) Ws[i] = W2[i];
    int base = blockIdx.x * 32;
    for (int i = tid; i < 32 * HID; i += 128) {
        int row = i >> 7;
        int col = i & 127;
        int gr = base + row;
        As2[row][col] = (gr < N_NODES) ? g_a1[(size_t)gr * HID + col] : 0.f;
    }
    __syncthreads();
    int nl = tid >> 2;
    int cg = (tid & 3) * 10;
    float acc[10] = {};
    #pragma unroll 8
    for (int k = 0; k < HID; k++) {
        float a = As2[nl][k];
        #pragma unroll
        for (int j = 0; j < 10; j++)
            acc[j] += a * Ws[k * NCLS + cg + j];
    }
    int gr = base + nl;
    if (gr < N_NODES) {
        #pragma unroll
        for (int j = 0; j < 10; j++)
            g_h2[(size_t)gr * NCLS + cg + j] = acc[j];
    }
}

// ---------------- agg2 + bias + log_softmax ----------------
__global__ void agg2_kernel(const float* __restrict__ b2, float* __restrict__ out) {
    int gw = (blockIdx.x * blockDim.x + threadIdx.x) >> 5;
    int lane = threadIdx.x & 31;
    if (gw >= N_NODES) return;
    int node = gw;
    const float* H = g_h2;
    float sd = g_invdeg[node];
    float acc0 = H[(size_t)node * NCLS + lane] * sd;
    float acc1 = (lane < 8) ? H[(size_t)node * NCLS + 32 + lane] * sd : 0.f;
    int s = g_start[node];
    int c = g_cnt[node];
    for (int e = 0; e < c; e++) {
        int2 ed = g_edge[s + e];
        int src  = ed.x;
        float cf = __int_as_float(ed.y);
        acc0 += H[(size_t)src * NCLS + lane] * cf;
        if (lane < 8) acc1 += H[(size_t)src * NCLS + 32 + lane] * cf;
    }
    acc0 += b2[lane];
    if (lane < 8) acc1 += b2[32 + lane];
    float m = acc0;
    if (lane < 8) m = fmaxf(m, acc1);
    #pragma unroll
    for (int off = 16; off > 0; off >>= 1)
        m = fmaxf(m, __shfl_xor_sync(0xffffffffu, m, off));
    float sum = expf(acc0 - m) + ((lane < 8) ? expf(acc1 - m) : 0.f);
    #pragma unroll
    for (int off = 16; off > 0; off >>= 1)
        sum += __shfl_xor_sync(0xffffffffu, sum, off);
    float lse = m + logf(sum);
    out[(size_t)node * NCLS + lane] = acc0 - lse;
    if (lane < 8) out[(size_t)node * NCLS + 32 + lane] = acc1 - lse;
}

// ---------------- launch ----------------
extern "C" void kernel_launch(void* const* d_in, const int* in_sizes, int n_in,
                              void* d_out, int out_size) {
    const float* x   = (const float*)d_in[0];
    const int*   ei  = (const int*)d_in[1];
    const float* W1  = (const float*)d_in[2];
    const float* b1  = (const float*)d_in[3];
    const float* W2  = (const float*)d_in[4];
    const float* b2  = (const float*)d_in[5];
    float* out = (float*)d_out;
    const int* src = ei;
    const int* dst = ei + N_EDGES;

    int nb_n = (N_NODES + 255) / 256;
    int nb_e = (N_EDGES + 255) / 256;

    zero_cnt_kernel<<<nb_n, 256>>>();
    count_kernel<<<nb_e, 256>>>(dst);
    scan_blocks_kernel<<<NBLK, SCAN_B>>>();
    scan_sums_kernel<<<1, 128>>>();
    finalize_nodes_kernel<<<nb_n, 256>>>();
    scatter_kernel<<<nb_e, 256>>>(src, dst);

    gemm1_mma_kernel<<<(N_NODES + 127) / 128, 256>>>(x, W1);

    agg1_kernel<<<(N_NODES + 7) / 8, 256>>>(b1);

    gemm2_kernel<<<(N_NODES + 31) / 32, 128>>>(W2);

    agg2_kernel<<<(N_NODES + 7) / 8, 256>>>(b2, out);
}